// round 1
// baseline (speedup 1.0000x reference)
#include <cuda_runtime.h>
#include <math.h>

// ---------------- configuration ----------------
#define NTH    256
#define G_MSE  1184      // MSE reduction blocks (148 SMs * 8)
#define G_STAT 128       // stats blocks
#define G_EN   256       // energy blocks
#define KK     4         // GMM components
#define DD     8         // latent dim
#define NSTAT  45        // 8 (Sz) + 36 (sym S2) + 1 (gamma sum)

#define EPS32_D 1.1920928955078125e-07   // float32 machine eps
#define TWOPI_P4 1558.5454565440389      // (2*pi)^4

// ---------------- device scratch (no allocations allowed) ----------------
__device__ float  g_mse_partial[G_MSE];
__device__ float  g_stat_partial[G_STAT][KK][NSTAT];
__device__ float  g_energy_partial[G_EN];
__device__ float  g_mu[KK][DD];
__device__ float  g_cinv[KK][DD * DD];
__device__ float  g_coef[KK];
__device__ double g_const_part;   // reconst_loss + 0.005*cov_diag

// ================= kernel 1: MSE partial sums =================
__global__ void __launch_bounds__(NTH) k_mse(const float* __restrict__ x,
                                             const float* __restrict__ xh,
                                             int n) {
    const int n4 = n >> 2;
    const float4* __restrict__ x4  = (const float4*)x;
    const float4* __restrict__ xh4 = (const float4*)xh;
    const int stride = G_MSE * NTH;
    int i = blockIdx.x * NTH + threadIdx.x;

    float acc = 0.f;
    // 4-way unrolled main loop for MLP
    for (; i + 3 * stride < n4; i += 4 * stride) {
        float4 a0 = x4[i],            b0 = xh4[i];
        float4 a1 = x4[i + stride],   b1 = xh4[i + stride];
        float4 a2 = x4[i + 2*stride], b2 = xh4[i + 2*stride];
        float4 a3 = x4[i + 3*stride], b3 = xh4[i + 3*stride];
        float d;
        d = b0.x - a0.x; acc += d*d;  d = b0.y - a0.y; acc += d*d;
        d = b0.z - a0.z; acc += d*d;  d = b0.w - a0.w; acc += d*d;
        d = b1.x - a1.x; acc += d*d;  d = b1.y - a1.y; acc += d*d;
        d = b1.z - a1.z; acc += d*d;  d = b1.w - a1.w; acc += d*d;
        d = b2.x - a2.x; acc += d*d;  d = b2.y - a2.y; acc += d*d;
        d = b2.z - a2.z; acc += d*d;  d = b2.w - a2.w; acc += d*d;
        d = b3.x - a3.x; acc += d*d;  d = b3.y - a3.y; acc += d*d;
        d = b3.z - a3.z; acc += d*d;  d = b3.w - a3.w; acc += d*d;
    }
    for (; i < n4; i += stride) {
        float4 a = x4[i], b = xh4[i];
        float d;
        d = b.x - a.x; acc += d*d;  d = b.y - a.y; acc += d*d;
        d = b.z - a.z; acc += d*d;  d = b.w - a.w; acc += d*d;
    }
    // scalar tail (n % 4)
    if (blockIdx.x == 0 && (int)threadIdx.x < (n & 3)) {
        int j = (n4 << 2) + threadIdx.x;
        float d = xh[j] - x[j];
        acc += d * d;
    }

    // block reduction (deterministic)
    #pragma unroll
    for (int o = 16; o; o >>= 1) acc += __shfl_xor_sync(0xffffffffu, acc, o);
    __shared__ float sw[NTH / 32];
    if ((threadIdx.x & 31) == 0) sw[threadIdx.x >> 5] = acc;
    __syncthreads();
    if (threadIdx.x == 0) {
        float s = 0.f;
        #pragma unroll
        for (int w = 0; w < NTH / 32; w++) s += sw[w];
        g_mse_partial[blockIdx.x] = s;
    }
}

// ================= kernel 2: GMM moment stats =================
// thread t handles component k = t&3 ; quads share a sample -> coalesced gamma,
// broadcast z. Accumulators: v[0..7]=sum(g*z), v[8..43]=sym sum(g*z_d*z_e),
// v[44]=sum(g).
__global__ void __launch_bounds__(NTH) k_stats(const float* __restrict__ z,
                                               const float* __restrict__ gamma,
                                               int n_samp) {
    const int t    = threadIdx.x;
    const int k    = t & 3;
    const int q0   = blockIdx.x * (NTH / 4) + (t >> 2);
    const int strd = G_STAT * (NTH / 4);
    const float4* __restrict__ z4 = (const float4*)z;

    float v[NSTAT];
    #pragma unroll
    for (int j = 0; j < NSTAT; j++) v[j] = 0.f;

    for (int s = q0; s < n_samp; s += strd) {
        float g = gamma[s * 4 + k];
        float4 a = z4[2 * s], b = z4[2 * s + 1];
        float zz[8] = {a.x, a.y, a.z, a.w, b.x, b.y, b.z, b.w};
        float gz[8];
        #pragma unroll
        for (int d = 0; d < 8; d++) { gz[d] = g * zz[d]; v[d] += gz[d]; }
        int c = 8;
        #pragma unroll
        for (int d = 0; d < 8; d++) {
            #pragma unroll
            for (int e = d; e < 8; e++) { v[c] += gz[d] * zz[e]; c++; }
        }
        v[44] += g;
    }

    // reduce across lanes with identical k (xor 4, 8, 16)
    #pragma unroll
    for (int j = 0; j < NSTAT; j++) {
        v[j] += __shfl_xor_sync(0xffffffffu, v[j], 4);
        v[j] += __shfl_xor_sync(0xffffffffu, v[j], 8);
        v[j] += __shfl_xor_sync(0xffffffffu, v[j], 16);
    }
    __shared__ float s_red[(NTH / 32) * 4][NSTAT];
    const int lane = t & 31, w = t >> 5;
    if (lane < 4) {
        #pragma unroll
        for (int j = 0; j < NSTAT; j++) s_red[w * 4 + lane][j] = v[j];
    }
    __syncthreads();
    if (t < 4 * NSTAT) {
        int kk = t & 3, j = t >> 2;
        float s = 0.f;
        #pragma unroll
        for (int ww = 0; ww < NTH / 32; ww++) s += s_red[ww * 4 + kk][j];
        g_stat_partial[blockIdx.x][kk][j] = s;
    }
}

// ================= kernel 3: parameters (1 block) =================
__global__ void __launch_bounds__(NTH) k_params(int n_x, int n_samp) {
    const int t = threadIdx.x;
    __shared__ double sd[NTH];
    __shared__ double s_reconst;
    __shared__ double s_stats[KK][NSTAT];
    __shared__ double s_covdiag[KK];

    // reduce MSE partials (fp64, fixed order)
    double a = 0.0;
    for (int i = t; i < G_MSE; i += NTH) a += (double)g_mse_partial[i];
    sd[t] = a;
    __syncthreads();
    for (int o = NTH / 2; o; o >>= 1) {
        if (t < o) sd[t] += sd[t + o];
        __syncthreads();
    }
    if (t == 0) s_reconst = sd[0] / (double)n_x;

    // reduce stat partials
    if (t < 4 * NSTAT) {
        int kk = t & 3, j = t >> 2;
        double s = 0.0;
        for (int b = 0; b < G_STAT; b++) s += (double)g_stat_partial[b][kk][j];
        s_stats[kk][j] = s;
    }
    __syncthreads();

    // warp w (< KK) handles component w: cov build + fp64 Gauss-Jordan inverse
    const int w = t >> 5, lane = t & 31;
    if (w < KK) {
        const int kk = w;
        double gsum = s_stats[kk][44];
        double gs   = gsum + EPS32_D;
        double phi  = gsum / ((double)n_samp + EPS32_D);

        double mu[8], Sz[8];
        #pragma unroll
        for (int d = 0; d < 8; d++) { Sz[d] = s_stats[kk][d]; mu[d] = Sz[d] / gs; }

        double row[16];
        #pragma unroll
        for (int c = 0; c < 16; c++) row[c] = 0.0;
        double cd = 0.0;
        if (lane < 8) {
            const int r = lane;
            #pragma unroll
            for (int c = 0; c < 8; c++) {
                int dm = r < c ? r : c, em = r < c ? c : r;
                int sidx = 8 + 7 * dm + em - (dm * (dm - 1)) / 2;
                double S2 = s_stats[kk][sidx];
                double cov = (S2 - mu[r] * Sz[c] - Sz[r] * mu[c] + gsum * mu[r] * mu[c]) / gs;
                if (r == c) cov += 1e-12;
                row[c] = cov;
            }
            row[8 + r] = 1.0;
            cd = 1.0 / row[r];
        }

        double det = 1.0;
        #pragma unroll
        for (int p = 0; p < 8; p++) {
            double app = __shfl_sync(0xffffffffu, row[p], p);
            det *= app;
            double m = row[p] / app;
            #pragma unroll
            for (int c = 0; c < 16; c++) {
                double pc = __shfl_sync(0xffffffffu, row[c], p);
                if (lane == p) row[c] = pc / app;
                else           row[c] -= m * pc;
            }
        }

        if (lane < 8) {
            #pragma unroll
            for (int c = 0; c < 8; c++) g_cinv[kk][lane * 8 + c] = (float)row[8 + c];
            g_mu[kk][lane] = (float)mu[lane];
        }
        // sum 1/diag over the 8 active lanes
        cd += __shfl_xor_sync(0xffffffffu, cd, 1);
        cd += __shfl_xor_sync(0xffffffffu, cd, 2);
        cd += __shfl_xor_sync(0xffffffffu, cd, 4);
        if (lane == 0) {
            s_covdiag[kk] = cd;
            double det_cov = TWOPI_P4 * sqrt(det);   // = prod(diag(chol(2*pi*Sigma)))
            g_coef[kk] = (float)(phi / sqrt(det_cov));
        }
    }
    __syncthreads();
    if (t == 0) {
        double cdall = s_covdiag[0] + s_covdiag[1] + s_covdiag[2] + s_covdiag[3];
        g_const_part = s_reconst + 0.005 * cdall;
    }
}

// ================= kernel 4: sample energy =================
__global__ void __launch_bounds__(NTH) k_energy(const float* __restrict__ z,
                                                int n_samp) {
    __shared__ float s_cinv[KK][DD * DD];
    __shared__ float s_mu[KK][DD];
    __shared__ float s_coef[KK];
    const int t = threadIdx.x;
    if (t < KK * DD * DD) s_cinv[t >> 6][t & 63] = g_cinv[t >> 6][t & 63];
    if (t < KK * DD)      s_mu[t >> 3][t & 7]    = g_mu[t >> 3][t & 7];
    if (t < KK)           s_coef[t]              = g_coef[t];
    __syncthreads();

    const float4* __restrict__ z4 = (const float4*)z;
    float acc = 0.f;
    for (int s = blockIdx.x * NTH + t; s < n_samp; s += G_EN * NTH) {
        float4 a = z4[2 * s], b = z4[2 * s + 1];
        float zz[8] = {a.x, a.y, a.z, a.w, b.x, b.y, b.z, b.w};
        float sum = 0.f;
        #pragma unroll
        for (int kk = 0; kk < KK; kk++) {
            float diff[8];
            #pragma unroll
            for (int d = 0; d < 8; d++) diff[d] = zz[d] - s_mu[kk][d];
            float q = 0.f;
            #pragma unroll
            for (int d = 0; d < 8; d++) {
                float td = 0.f;
                #pragma unroll
                for (int e = 0; e < 8; e++) td += s_cinv[kk][d * 8 + e] * diff[e];
                q += diff[d] * td;
            }
            sum += s_coef[kk] * __expf(-0.5f * q);
        }
        acc += -__logf(sum + 1e-12f);
    }

    #pragma unroll
    for (int o = 16; o; o >>= 1) acc += __shfl_xor_sync(0xffffffffu, acc, o);
    __shared__ float sw[NTH / 32];
    if ((t & 31) == 0) sw[t >> 5] = acc;
    __syncthreads();
    if (t == 0) {
        float s = 0.f;
        #pragma unroll
        for (int ww = 0; ww < NTH / 32; ww++) s += sw[ww];
        g_energy_partial[blockIdx.x] = s;
    }
}

// ================= kernel 5: final combine =================
__global__ void __launch_bounds__(NTH) k_final(float* __restrict__ out,
                                               int out_size, int n_samp) {
    const int t = threadIdx.x;
    __shared__ double sd[NTH];
    double a = 0.0;
    for (int i = t; i < G_EN; i += NTH) a += (double)g_energy_partial[i];
    sd[t] = a;
    __syncthreads();
    for (int o = NTH / 2; o; o >>= 1) {
        if (t < o) sd[t] += sd[t + o];
        __syncthreads();
    }
    double loss = g_const_part + 0.1 * (sd[0] / (double)n_samp);
    for (int i = t; i < out_size; i += NTH) out[i] = (float)loss;
}

// ================= launch =================
extern "C" void kernel_launch(void* const* d_in, const int* in_sizes, int n_in,
                              void* d_out, int out_size) {
    const float* x     = (const float*)d_in[0];
    const float* x_hat = (const float*)d_in[1];
    const float* z     = (const float*)d_in[2];
    const float* gamma = (const float*)d_in[3];
    const int n_x    = in_sizes[0];
    const int n_samp = in_sizes[2] / DD;   // B*C*T

    k_mse<<<G_MSE, NTH>>>(x, x_hat, n_x);
    k_stats<<<G_STAT, NTH>>>(z, gamma, n_samp);
    k_params<<<1, NTH>>>(n_x, n_samp);
    k_energy<<<G_EN, NTH>>>(z, n_samp);
    k_final<<<1, NTH>>>((float*)d_out, out_size, n_samp);
}

// round 4
// speedup vs baseline: 1.1636x; 1.1636x over previous
#include <cuda_runtime.h>
#include <math.h>

// ---------------- configuration ----------------
#define NTH    256
#define G_MSE  1024      // MSE blocks inside fused kernel
#define G_STAT 256       // stats blocks inside fused kernel
#define G_EN   512       // energy blocks
#define KK     4
#define DD     8
#define NSTAT  45        // 8 (Sz) + 36 (sym S2) + 1 (gamma sum)
#define NSYM   36

#define EPS32_D 1.1920928955078125e-07
#define TWOPI_P4 1558.5454565440389      // (2*pi)^4

// ---------------- device scratch ----------------
__device__ float  g_mse_partial[G_MSE];
__device__ float  g_stat_partial[G_STAT][KK][NSTAT];
__device__ float  g_energy_partial[G_EN];
__device__ float  g_mu[KK][DD];
__device__ float  g_esym[KK][NSYM];   // weighted sym inverse: diag*1, offdiag*2
__device__ float  g_coef[KK];         // phi_k / sqrt(det_cov_k)
__device__ double g_const_part;       // reconst + 0.005*cov_diag

// ================= kernel 1: fused MSE + GMM stats =================
__global__ void __launch_bounds__(NTH) k_fused(const float* __restrict__ x,
                                               const float* __restrict__ xh,
                                               const float* __restrict__ z,
                                               const float* __restrict__ gamma,
                                               int n, int n_samp) {
    if (blockIdx.x < G_MSE) {
        // ---------- MSE part ----------
        const int n4 = n >> 2;
        const float4* __restrict__ x4  = (const float4*)x;
        const float4* __restrict__ xh4 = (const float4*)xh;
        const int stride = G_MSE * NTH;
        int i = blockIdx.x * NTH + threadIdx.x;

        float acc = 0.f;
        for (; i + 3 * stride < n4; i += 4 * stride) {
            float4 a0 = x4[i],            b0 = xh4[i];
            float4 a1 = x4[i + stride],   b1 = xh4[i + stride];
            float4 a2 = x4[i + 2*stride], b2 = xh4[i + 2*stride];
            float4 a3 = x4[i + 3*stride], b3 = xh4[i + 3*stride];
            float d;
            d = b0.x - a0.x; acc += d*d;  d = b0.y - a0.y; acc += d*d;
            d = b0.z - a0.z; acc += d*d;  d = b0.w - a0.w; acc += d*d;
            d = b1.x - a1.x; acc += d*d;  d = b1.y - a1.y; acc += d*d;
            d = b1.z - a1.z; acc += d*d;  d = b1.w - a1.w; acc += d*d;
            d = b2.x - a2.x; acc += d*d;  d = b2.y - a2.y; acc += d*d;
            d = b2.z - a2.z; acc += d*d;  d = b2.w - a2.w; acc += d*d;
            d = b3.x - a3.x; acc += d*d;  d = b3.y - a3.y; acc += d*d;
            d = b3.z - a3.z; acc += d*d;  d = b3.w - a3.w; acc += d*d;
        }
        for (; i < n4; i += stride) {
            float4 a = x4[i], b = xh4[i];
            float d;
            d = b.x - a.x; acc += d*d;  d = b.y - a.y; acc += d*d;
            d = b.z - a.z; acc += d*d;  d = b.w - a.w; acc += d*d;
        }
        if (blockIdx.x == 0 && (int)threadIdx.x < (n & 3)) {
            int j = (n4 << 2) + threadIdx.x;
            float d = xh[j] - x[j];
            acc += d * d;
        }

        #pragma unroll
        for (int o = 16; o; o >>= 1) acc += __shfl_xor_sync(0xffffffffu, acc, o);
        __shared__ float sw[NTH / 32];
        if ((threadIdx.x & 31) == 0) sw[threadIdx.x >> 5] = acc;
        __syncthreads();
        if (threadIdx.x == 0) {
            float s = 0.f;
            #pragma unroll
            for (int w = 0; w < NTH / 32; w++) s += sw[w];
            g_mse_partial[blockIdx.x] = s;
        }
    } else {
        // ---------- GMM moment stats part ----------
        const int bid  = blockIdx.x - G_MSE;
        const int t    = threadIdx.x;
        const int k    = t & 3;
        const int q0   = bid * (NTH / 4) + (t >> 2);
        const int strd = G_STAT * (NTH / 4);
        const float4* __restrict__ z4 = (const float4*)z;

        float v[NSTAT];
        #pragma unroll
        for (int j = 0; j < NSTAT; j++) v[j] = 0.f;

        for (int s = q0; s < n_samp; s += strd) {
            float g = gamma[s * 4 + k];
            float4 a = z4[2 * s], b = z4[2 * s + 1];
            float zz[8] = {a.x, a.y, a.z, a.w, b.x, b.y, b.z, b.w};
            float gz[8];
            #pragma unroll
            for (int d = 0; d < 8; d++) { gz[d] = g * zz[d]; v[d] += gz[d]; }
            int c = 8;
            #pragma unroll
            for (int d = 0; d < 8; d++) {
                #pragma unroll
                for (int e = d; e < 8; e++) { v[c] += gz[d] * zz[e]; c++; }
            }
            v[44] += g;
        }

        #pragma unroll
        for (int j = 0; j < NSTAT; j++) {
            v[j] += __shfl_xor_sync(0xffffffffu, v[j], 4);
            v[j] += __shfl_xor_sync(0xffffffffu, v[j], 8);
            v[j] += __shfl_xor_sync(0xffffffffu, v[j], 16);
        }
        __shared__ float s_red[(NTH / 32) * 4][NSTAT];
        const int lane = t & 31, w = t >> 5;
        if (lane < 4) {
            #pragma unroll
            for (int j = 0; j < NSTAT; j++) s_red[w * 4 + lane][j] = v[j];
        }
        __syncthreads();
        if (t < 4 * NSTAT) {
            int kk = t & 3, j = t >> 2;
            float s = 0.f;
            #pragma unroll
            for (int ww = 0; ww < NTH / 32; ww++) s += s_red[ww * 4 + kk][j];
            g_stat_partial[bid][kk][j] = s;
        }
    }
}

// ================= kernel 2: parameters (1 block) =================
__global__ void __launch_bounds__(NTH) k_params(int n_x, int n_samp) {
    const int t = threadIdx.x;
    __shared__ double sd[NTH];
    __shared__ double s_reconst;
    __shared__ double s_stats[KK][NSTAT];
    __shared__ double s_covdiag[KK];

    double a = 0.0;
    for (int i = t; i < G_MSE; i += NTH) a += (double)g_mse_partial[i];
    sd[t] = a;
    __syncthreads();
    for (int o = NTH / 2; o; o >>= 1) {
        if (t < o) sd[t] += sd[t + o];
        __syncthreads();
    }
    if (t == 0) s_reconst = sd[0] / (double)n_x;

    if (t < 4 * NSTAT) {
        int kk = t & 3, j = t >> 2;
        double s = 0.0;
        for (int b = 0; b < G_STAT; b++) s += (double)g_stat_partial[b][kk][j];
        s_stats[kk][j] = s;
    }
    __syncthreads();

    const int w = t >> 5, lane = t & 31;
    if (w < KK) {
        const int kk = w;
        double gsum = s_stats[kk][44];
        double gs   = gsum + EPS32_D;
        double phi  = gsum / ((double)n_samp + EPS32_D);

        double mu[8], Sz[8];
        #pragma unroll
        for (int d = 0; d < 8; d++) { Sz[d] = s_stats[kk][d]; mu[d] = Sz[d] / gs; }

        double row[16];
        #pragma unroll
        for (int c = 0; c < 16; c++) row[c] = 0.0;
        double cd = 0.0;
        if (lane < 8) {
            const int r = lane;
            #pragma unroll
            for (int c = 0; c < 8; c++) {
                int dm = r < c ? r : c, em = r < c ? c : r;
                int sidx = 8 + 7 * dm + em - (dm * (dm - 1)) / 2;
                double S2 = s_stats[kk][sidx];
                double cov = (S2 - mu[r] * Sz[c] - Sz[r] * mu[c] + gsum * mu[r] * mu[c]) / gs;
                if (r == c) cov += 1e-12;
                row[c] = cov;
            }
            row[8 + r] = 1.0;
            cd = 1.0 / row[r];
        }

        double det = 1.0;
        #pragma unroll
        for (int p = 0; p < 8; p++) {
            double app = __shfl_sync(0xffffffffu, row[p], p);
            det *= app;
            double m = row[p] / app;
            #pragma unroll
            for (int c = 0; c < 16; c++) {
                double pc = __shfl_sync(0xffffffffu, row[c], p);
                if (lane == p) row[c] = pc / app;
                else           row[c] -= m * pc;
            }
        }

        if (lane < 8) {
            const int r = lane;
            // weighted symmetric inverse: diag*1, offdiag*2 (for c >= r)
            #pragma unroll
            for (int c = 0; c < 8; c++) {
                if (c >= r) {
                    int j = 7 * r + c - (r * (r - 1)) / 2;  // 0..35
                    double wv = (c == r ? 1.0 : 2.0) * row[8 + c];
                    g_esym[kk][j] = (float)wv;
                }
            }
            g_mu[kk][r] = (float)mu[r];
        }
        cd += __shfl_xor_sync(0xffffffffu, cd, 1);
        cd += __shfl_xor_sync(0xffffffffu, cd, 2);
        cd += __shfl_xor_sync(0xffffffffu, cd, 4);
        if (lane == 0) {
            s_covdiag[kk] = cd;
            double det_cov = TWOPI_P4 * sqrt(det);
            g_coef[kk] = (float)(phi / sqrt(det_cov));
        }
    }
    __syncthreads();
    if (t == 0) {
        double cdall = s_covdiag[0] + s_covdiag[1] + s_covdiag[2] + s_covdiag[3];
        g_const_part = s_reconst + 0.005 * cdall;
    }
}

// ================= kernel 3: sample energy =================
// thread t handles component k = t&3; quad shares a sample. Per-thread
// constants (36 weighted sym inverse + 8 mu + coef) are register-resident.
__global__ void __launch_bounds__(NTH) k_energy(const float* __restrict__ z,
                                                int n_samp) {
    const int t = threadIdx.x;
    const int k = t & 3;

    float wsym[NSYM], mu[DD], coef;
    #pragma unroll
    for (int j = 0; j < NSYM; j++) wsym[j] = g_esym[k][j];
    #pragma unroll
    for (int d = 0; d < DD; d++) mu[d] = g_mu[k][d];
    coef = g_coef[k];

    const float4* __restrict__ z4 = (const float4*)z;
    const int q0   = blockIdx.x * (NTH / 4) + (t >> 2);
    const int strd = G_EN * (NTH / 4);

    float acc = 0.f;
    #pragma unroll 2
    for (int s = q0; s < n_samp; s += strd) {
        float4 a = z4[2 * s], b = z4[2 * s + 1];
        float diff[8] = {a.x - mu[0], a.y - mu[1], a.z - mu[2], a.w - mu[3],
                         b.x - mu[4], b.y - mu[5], b.z - mu[6], b.w - mu[7]};
        float q = 0.f;
        int c = 0;
        #pragma unroll
        for (int d = 0; d < 8; d++) {
            #pragma unroll
            for (int e = d; e < 8; e++) { q += wsym[c] * (diff[d] * diff[e]); c++; }
        }
        float term = coef * __expf(-0.5f * q);
        // sum the 4 component terms within the quad
        term += __shfl_xor_sync(0xffffffffu, term, 1);
        term += __shfl_xor_sync(0xffffffffu, term, 2);
        acc += -__logf(term + 1e-12f);   // identical on all 4 quad lanes -> /4 later
    }

    #pragma unroll
    for (int o = 16; o; o >>= 1) acc += __shfl_xor_sync(0xffffffffu, acc, o);
    __shared__ float sw[NTH / 32];
    if ((t & 31) == 0) sw[t >> 5] = acc;
    __syncthreads();
    if (t == 0) {
        float s2 = 0.f;
        #pragma unroll
        for (int ww = 0; ww < NTH / 32; ww++) s2 += sw[ww];
        g_energy_partial[blockIdx.x] = s2;
    }
}

// ================= kernel 4: final combine =================
__global__ void __launch_bounds__(NTH) k_final(float* __restrict__ out,
                                               int out_size, int n_samp) {
    const int t = threadIdx.x;
    __shared__ double sd[NTH];
    double a = 0.0;
    for (int i = t; i < G_EN; i += NTH) a += (double)g_energy_partial[i];
    sd[t] = a;
    __syncthreads();
    for (int o = NTH / 2; o; o >>= 1) {
        if (t < o) sd[t] += sd[t + o];
        __syncthreads();
    }
    // each quad-lane accumulated the same -log -> divide by 4
    double loss = g_const_part + 0.1 * (sd[0] / (4.0 * (double)n_samp));
    for (int i = t; i < out_size; i += NTH) out[i] = (float)loss;
}

// ================= launch =================
extern "C" void kernel_launch(void* const* d_in, const int* in_sizes, int n_in,
                              void* d_out, int out_size) {
    const float* x     = (const float*)d_in[0];
    const float* x_hat = (const float*)d_in[1];
    const float* z     = (const float*)d_in[2];
    const float* gamma = (const float*)d_in[3];
    const int n_x    = in_sizes[0];
    const int n_samp = in_sizes[2] / DD;

    k_fused<<<G_MSE + G_STAT, NTH>>>(x, x_hat, z, gamma, n_x, n_samp);
    k_params<<<1, NTH>>>(n_x, n_samp);
    k_energy<<<G_EN, NTH>>>(z, n_samp);
    k_final<<<1, NTH>>>((float*)d_out, out_size, n_samp);
}